// round 5
// baseline (speedup 1.0000x reference)
#include <cuda_runtime.h>
#include <cuda_bf16.h>
#include <cstdint>

#define KDIM 1024
#define IDIM 64
#define ODIM 1024
#define THREADS 128
#define NT 64                  // N tile per CTA
#define KC 16                  // fp32 k per chunk
#define NCHUNK (KDIM / KC)     // 64

#define ROWB 48                // bf16 row: 32B data + 16B pad (conflict-free LDSM)
#define T_AH 0
#define T_AL (128 * ROWB)              // 6144
#define T_BH (2 * 128 * ROWB)          // 12288
#define T_BL (T_BH + NT * ROWB)        // 15360
#define BUF_SZ (T_BH + 2 * NT * ROWB)  // 18432

#define OFF_STG (2 * BUF_SZ)           // 36864
#define STG_B_OFF (128 * KC * 4)       // 8192
#define STG_SZ (STG_B_OFF + NT * KC * 4)  // 12288
#define SMEM_DYN (OFF_STG + STG_SZ)    // 49152 = 48KB -> 4 CTAs/SM

static __device__ __forceinline__ uint32_t smem_u32(const void* p) {
    uint32_t a;
    asm("{ .reg .u64 t; cvta.to.shared.u64 t, %1; cvt.u32.u64 %0, t; }"
        : "=r"(a) : "l"(p));
    return a;
}

static __device__ __forceinline__ void ldm_x4(uint32_t* r, uint32_t addr) {
    asm volatile(
        "ldmatrix.sync.aligned.m8n8.x4.shared.b16 {%0,%1,%2,%3}, [%4];"
        : "=r"(r[0]), "=r"(r[1]), "=r"(r[2]), "=r"(r[3]) : "r"(addr));
}

static __device__ __forceinline__ void mma_bf16(float* d, const uint32_t* a,
                                                const uint32_t* b) {
    asm volatile(
        "mma.sync.aligned.m16n8k16.row.col.f32.bf16.bf16.f32 "
        "{%0,%1,%2,%3}, {%4,%5,%6,%7}, {%8,%9}, {%0,%1,%2,%3};"
        : "+f"(d[0]), "+f"(d[1]), "+f"(d[2]), "+f"(d[3])
        : "r"(a[0]), "r"(a[1]), "r"(a[2]), "r"(a[3]), "r"(b[0]), "r"(b[1]));
}

static __device__ __forceinline__ void cp16(uint32_t saddr, const void* gaddr) {
    asm volatile("cp.async.cg.shared.global [%0], [%1], 16;"
                 :: "r"(saddr), "l"(gaddr));
}

// Stage one K-chunk: A [128 x 16] f32 + B [64 x 16] f32. Each thread stages
// exactly the float4s it later converts (self-consumed, program-ordered).
static __device__ __forceinline__ void stage_chunk(uint32_t stg,
                                                   const float* __restrict__ ga,
                                                   const float* __restrict__ gb) {
    const int tid = threadIdx.x;
#pragma unroll
    for (int it = 0; it < 4; ++it) {           // A: 512 float4
        int f = tid + it * THREADS;
        int row = f >> 2;
        int c4 = f & 3;
        cp16(stg + (uint32_t)(f * 16), ga + (size_t)row * 65536 + c4 * 4);
    }
#pragma unroll
    for (int it = 0; it < 2; ++it) {           // B: 256 float4
        int f = tid + it * THREADS;
        int row = f >> 2;
        int c4 = f & 3;
        cp16(stg + STG_B_OFF + (uint32_t)(f * 16),
             gb + (size_t)row * 65536 + c4 * 4);
    }
    asm volatile("cp.async.commit_group;" ::: "memory");
}

static __device__ __forceinline__ void cvt4(const float4 v, uint2* hi, uint2* lo) {
    __nv_bfloat16 h0 = __float2bfloat16_rn(v.x);
    __nv_bfloat16 h1 = __float2bfloat16_rn(v.y);
    __nv_bfloat16 h2 = __float2bfloat16_rn(v.z);
    __nv_bfloat16 h3 = __float2bfloat16_rn(v.w);
    __nv_bfloat16 l0 = __float2bfloat16_rn(v.x - __bfloat162float(h0));
    __nv_bfloat16 l1 = __float2bfloat16_rn(v.y - __bfloat162float(h1));
    __nv_bfloat16 l2 = __float2bfloat16_rn(v.z - __bfloat162float(h2));
    __nv_bfloat16 l3 = __float2bfloat16_rn(v.w - __bfloat162float(h3));
    hi->x = (uint32_t)__bfloat16_as_ushort(h0) | ((uint32_t)__bfloat16_as_ushort(h1) << 16);
    hi->y = (uint32_t)__bfloat16_as_ushort(h2) | ((uint32_t)__bfloat16_as_ushort(h3) << 16);
    lo->x = (uint32_t)__bfloat16_as_ushort(l0) | ((uint32_t)__bfloat16_as_ushort(l1) << 16);
    lo->y = (uint32_t)__bfloat16_as_ushort(l2) | ((uint32_t)__bfloat16_as_ushort(l3) << 16);
}

// Convert own staged fp32 -> bf16 hi/lo padded tiles.
static __device__ __forceinline__ void convert_stage(char* sm, uint32_t buf_off) {
    const int tid = threadIdx.x;
#pragma unroll
    for (int it = 0; it < 4; ++it) {           // A
        int f = tid + it * THREADS;
        int row = f >> 2;
        int c4 = f & 3;
        const float4 v = *reinterpret_cast<const float4*>(sm + OFF_STG + f * 16);
        uint2 hi, lo;
        cvt4(v, &hi, &lo);
        uint32_t dst = (uint32_t)(row * ROWB + c4 * 8);
        *reinterpret_cast<uint2*>(sm + buf_off + T_AH + dst) = hi;
        *reinterpret_cast<uint2*>(sm + buf_off + T_AL + dst) = lo;
    }
#pragma unroll
    for (int it = 0; it < 2; ++it) {           // B
        int f = tid + it * THREADS;
        int row = f >> 2;
        int c4 = f & 3;
        const float4 v = *reinterpret_cast<const float4*>(
            sm + OFF_STG + STG_B_OFF + f * 16);
        uint2 hi, lo;
        cvt4(v, &hi, &lo);
        uint32_t dst = (uint32_t)(row * ROWB + c4 * 8);
        *reinterpret_cast<uint2*>(sm + buf_off + T_BH + dst) = hi;
        *reinterpret_cast<uint2*>(sm + buf_off + T_BL + dst) = lo;
    }
}

__global__ void __launch_bounds__(THREADS, 4)
fl_kernel(const float* __restrict__ x, const float* __restrict__ w,
          const float* __restrict__ bias, float* __restrict__ out) {
    extern __shared__ char sm[];
    const uint32_t sbase = smem_u32(sm);
    const int tid = threadIdx.x;
    const int wid = tid >> 5;
    const int lid = tid & 31;
    const int warp_m = wid >> 1;   // 0..1 : 64 M rows each
    const int warp_n = wid & 1;    // 0..1 : 32 N cols each
    const int otile = blockIdx.x;  // 0..15
    const int i_idx = blockIdx.y;  // 0..63

    const float* xa = x + (size_t)i_idx * KDIM;
    const float* wa = w + ((size_t)otile * NT) * (IDIM * KDIM) + (size_t)i_idx * KDIM;

    float acc[4][4][4];
#pragma unroll
    for (int a = 0; a < 4; ++a)
#pragma unroll
        for (int b = 0; b < 4; ++b)
#pragma unroll
            for (int c = 0; c < 4; ++c) acc[a][b][c] = 0.0f;

    const uint32_t a_row = (uint32_t)(warp_m * 64 + (lid & 15));
    const uint32_t a_cb = (uint32_t)((lid >> 4) * 16);
    const uint32_t b_row = (uint32_t)(warp_n * 32 + ((lid >> 4) << 3) + (lid & 7));
    const uint32_t b_cb = (uint32_t)(((lid >> 3) & 1) * 16);

    // Prologue: stage chunk 0, convert into buf 0.
    stage_chunk(sbase + OFF_STG, xa, wa);
    asm volatile("cp.async.wait_group 0;" ::: "memory");
    convert_stage(sm, 0);
    __syncthreads();

    for (int ch = 0; ch < NCHUNK; ++ch) {
        // Prefetch chunk ch+1 (stage buffer was self-consumed last iteration).
        if (ch + 1 < NCHUNK) {
            stage_chunk(sbase + OFF_STG, xa + (ch + 1) * KC, wa + (ch + 1) * KC);
        }

        // MMA on buf[ch&1]
        const uint32_t buf = sbase + (uint32_t)((ch & 1) * BUF_SZ);
        uint32_t ah[4][4], al[4][4], bh[2][4], bl[2][4];
#pragma unroll
        for (int mt = 0; mt < 4; ++mt) {
            uint32_t addr = buf + T_AH + (a_row + mt * 16) * ROWB + a_cb;
            ldm_x4(ah[mt], addr);
            ldm_x4(al[mt], addr + (T_AL - T_AH));
        }
#pragma unroll
        for (int bt = 0; bt < 2; ++bt) {
            uint32_t addr = buf + T_BH + (b_row + bt * 16) * ROWB + b_cb;
            ldm_x4(bh[bt], addr);
            ldm_x4(bl[bt], addr + (T_BL - T_BH));
        }
#pragma unroll
        for (int mt = 0; mt < 4; ++mt)
#pragma unroll
            for (int nt = 0; nt < 4; ++nt)
                mma_bf16(acc[mt][nt], ah[mt], &bh[nt >> 1][(nt & 1) * 2]);
#pragma unroll
        for (int mt = 0; mt < 4; ++mt)
#pragma unroll
            for (int nt = 0; nt < 4; ++nt)
                mma_bf16(acc[mt][nt], ah[mt], &bl[nt >> 1][(nt & 1) * 2]);
#pragma unroll
        for (int mt = 0; mt < 4; ++mt)
#pragma unroll
            for (int nt = 0; nt < 4; ++nt)
                mma_bf16(acc[mt][nt], al[mt], &bh[nt >> 1][(nt & 1) * 2]);

        // Convert chunk ch+1 into buf[(ch+1)&1] (own staged data only)
        asm volatile("cp.async.wait_group 0;" ::: "memory");
        if (ch + 1 < NCHUNK) {
            convert_stage(sm, (uint32_t)(((ch + 1) & 1) * BUF_SZ));
        }
        __syncthreads();
    }

    // Epilogue: add bias, store. out[b][o][i] = b*65536 + o*64 + i
    const float* bp = bias + (size_t)(otile * NT) * IDIM + i_idx;
    float bv[4][2];
#pragma unroll
    for (int nt = 0; nt < 4; ++nt) {
        int n_l = warp_n * 32 + nt * 8 + 2 * (lid & 3);
        bv[nt][0] = bp[(size_t)n_l * IDIM];
        bv[nt][1] = bp[(size_t)(n_l + 1) * IDIM];
    }
#pragma unroll
    for (int mt = 0; mt < 4; ++mt) {
        int m0 = warp_m * 64 + mt * 16 + (lid >> 2);
#pragma unroll
        for (int nt = 0; nt < 4; ++nt) {
            int n_l = warp_n * 32 + nt * 8 + 2 * (lid & 3);
            float* o0 = out + (size_t)m0 * (ODIM * IDIM) +
                        (size_t)(otile * NT + n_l) * IDIM + i_idx;
            o0[0] = acc[mt][nt][0] + bv[nt][0];
            o0[IDIM] = acc[mt][nt][1] + bv[nt][1];
            float* o8 = o0 + (size_t)8 * (ODIM * IDIM);
            o8[0] = acc[mt][nt][2] + bv[nt][0];
            o8[IDIM] = acc[mt][nt][3] + bv[nt][1];
        }
    }
}

extern "C" void kernel_launch(void* const* d_in, const int* in_sizes, int n_in,
                              void* d_out, int out_size) {
    (void)in_sizes; (void)n_in; (void)out_size;
    const float* x = (const float*)d_in[0];
    const float* w = (const float*)d_in[1];
    const float* bias = (const float*)d_in[2];
    float* out = (float*)d_out;

    cudaFuncSetAttribute(fl_kernel, cudaFuncAttributeMaxDynamicSharedMemorySize,
                         SMEM_DYN);
    fl_kernel<<<dim3(ODIM / NT, IDIM), THREADS, SMEM_DYN>>>(x, w, bias, out);
}

// round 6
// speedup vs baseline: 1.2774x; 1.2774x over previous
#include <cuda_runtime.h>
#include <cuda_fp16.h>
#include <cstdint>

#define KDIM 1024
#define IDIM 64
#define ODIM 1024
#define THREADS 256
#define KC 32                  // fp32 k per chunk
#define NCHUNK (KDIM / KC)     // 32

#define ROWB 80                // fp16 tile row: 64B data + 16B pad (conflict-free LDSM)
#define TILE_B (128 * ROWB)    // 10240
#define BUF_SZ (3 * TILE_B)    // 30720: AH, BH, BL (no A-lo tile)
#define T_AH 0
#define T_BH TILE_B
#define T_BL (2 * TILE_B)

#define OFF_STG (2 * BUF_SZ)       // 61440 (single fp32 stage buffer)
#define STG_B_OFF (128 * KC * 4)   // 16384
#define STG_SZ (2 * 128 * KC * 4)  // 32768 (A + B fp32)
#define SMEM_DYN (OFF_STG + STG_SZ)  // 94208 = 92KB -> 2 CTAs/SM

static __device__ __forceinline__ uint32_t smem_u32(const void* p) {
    uint32_t a;
    asm("{ .reg .u64 t; cvta.to.shared.u64 t, %1; cvt.u32.u64 %0, t; }"
        : "=r"(a) : "l"(p));
    return a;
}

static __device__ __forceinline__ void ldm_x4(uint32_t* r, uint32_t addr) {
    asm volatile(
        "ldmatrix.sync.aligned.m8n8.x4.shared.b16 {%0,%1,%2,%3}, [%4];"
        : "=r"(r[0]), "=r"(r[1]), "=r"(r[2]), "=r"(r[3]) : "r"(addr));
}

static __device__ __forceinline__ void mma_f16(float* d, const uint32_t* a,
                                               const uint32_t* b) {
    asm volatile(
        "mma.sync.aligned.m16n8k16.row.col.f32.f16.f16.f32 "
        "{%0,%1,%2,%3}, {%4,%5,%6,%7}, {%8,%9}, {%0,%1,%2,%3};"
        : "+f"(d[0]), "+f"(d[1]), "+f"(d[2]), "+f"(d[3])
        : "r"(a[0]), "r"(a[1]), "r"(a[2]), "r"(a[3]), "r"(b[0]), "r"(b[1]));
}

static __device__ __forceinline__ void cp16(uint32_t saddr, const void* gaddr) {
    asm volatile("cp.async.cg.shared.global [%0], [%1], 16;"
                 :: "r"(saddr), "l"(gaddr));
}

// Stage one K-chunk: A [128 x 32] f32 + B [128 x 32] f32. Each thread stages the
// exact float4s it later converts (self-consumed, program-ordered).
static __device__ __forceinline__ void stage_chunk(uint32_t stg,
                                                   const float* __restrict__ ga,
                                                   const float* __restrict__ gb) {
    const int tid = threadIdx.x;
#pragma unroll
    for (int it = 0; it < 4; ++it) {
        int f = tid + it * THREADS;     // float4 idx 0..1023
        int row = f >> 3;
        int c4 = f & 7;
        cp16(stg + (uint32_t)(f * 16), ga + (size_t)row * 65536 + c4 * 4);
        cp16(stg + STG_B_OFF + (uint32_t)(f * 16), gb + (size_t)row * 65536 + c4 * 4);
    }
    asm volatile("cp.async.commit_group;" ::: "memory");
}

static __device__ __forceinline__ uint2 pack_hi4(const float4 v) {
    __half h0 = __float2half_rn(v.x), h1 = __float2half_rn(v.y);
    __half h2 = __float2half_rn(v.z), h3 = __float2half_rn(v.w);
    uint2 r;
    r.x = (uint32_t)__half_as_ushort(h0) | ((uint32_t)__half_as_ushort(h1) << 16);
    r.y = (uint32_t)__half_as_ushort(h2) | ((uint32_t)__half_as_ushort(h3) << 16);
    return r;
}

// Convert own staged fp32 -> fp16 tiles. A: hi only. B: hi + residual lo.
static __device__ __forceinline__ void convert_stage(char* sm, uint32_t buf_off) {
    const int tid = threadIdx.x;
#pragma unroll
    for (int it = 0; it < 4; ++it) {
        int f = tid + it * THREADS;
        int row = f >> 3;
        int c4 = f & 7;
        uint32_t dst = (uint32_t)(row * ROWB + c4 * 8);

        // A: hi only
        const float4 va = *reinterpret_cast<const float4*>(sm + OFF_STG + f * 16);
        *reinterpret_cast<uint2*>(sm + buf_off + T_AH + dst) = pack_hi4(va);

        // B: hi + lo
        const float4 vb = *reinterpret_cast<const float4*>(
            sm + OFF_STG + STG_B_OFF + f * 16);
        __half h0 = __float2half_rn(vb.x), h1 = __float2half_rn(vb.y);
        __half h2 = __float2half_rn(vb.z), h3 = __float2half_rn(vb.w);
        __half l0 = __float2half_rn(vb.x - __half2float(h0));
        __half l1 = __float2half_rn(vb.y - __half2float(h1));
        __half l2 = __float2half_rn(vb.z - __half2float(h2));
        __half l3 = __float2half_rn(vb.w - __half2float(h3));
        uint2 hi, lo;
        hi.x = (uint32_t)__half_as_ushort(h0) | ((uint32_t)__half_as_ushort(h1) << 16);
        hi.y = (uint32_t)__half_as_ushort(h2) | ((uint32_t)__half_as_ushort(h3) << 16);
        lo.x = (uint32_t)__half_as_ushort(l0) | ((uint32_t)__half_as_ushort(l1) << 16);
        lo.y = (uint32_t)__half_as_ushort(l2) | ((uint32_t)__half_as_ushort(l3) << 16);
        *reinterpret_cast<uint2*>(sm + buf_off + T_BH + dst) = hi;
        *reinterpret_cast<uint2*>(sm + buf_off + T_BL + dst) = lo;
    }
}

__global__ void __launch_bounds__(THREADS, 2)
fl_kernel(const float* __restrict__ x, const float* __restrict__ w,
          const float* __restrict__ bias, float* __restrict__ out) {
    extern __shared__ char sm[];
    const uint32_t sbase = smem_u32(sm);
    const int tid = threadIdx.x;
    const int wid = tid >> 5;
    const int lid = tid & 31;
    const int warp_m = wid >> 2;   // 0..1 : 64 M rows each
    const int warp_n = wid & 3;    // 0..3 : 32 N cols each
    const int otile = blockIdx.x;  // 0..7
    const int i_idx = blockIdx.y;  // 0..63

    const float* xa = x + (size_t)i_idx * KDIM;
    const float* wa = w + ((size_t)otile * 128) * (IDIM * KDIM) + (size_t)i_idx * KDIM;

    float acc[4][4][4];
#pragma unroll
    for (int a = 0; a < 4; ++a)
#pragma unroll
        for (int b = 0; b < 4; ++b)
#pragma unroll
            for (int c = 0; c < 4; ++c) acc[a][b][c] = 0.0f;

    const uint32_t a_row = (uint32_t)(warp_m * 64 + (lid & 15));
    const uint32_t a_cb = (uint32_t)((lid >> 4) * 16);
    const uint32_t b_row = (uint32_t)(warp_n * 32 + ((lid >> 4) << 3) + (lid & 7));
    const uint32_t b_cb = (uint32_t)(((lid >> 3) & 1) * 16);

    // Prologue: stage chunk 0, convert into buf 0.
    stage_chunk(sbase + OFF_STG, xa, wa);
    asm volatile("cp.async.wait_group 0;" ::: "memory");
    convert_stage(sm, 0);
    __syncthreads();

    for (int ch = 0; ch < NCHUNK; ++ch) {
        // Prefetch chunk ch+1 (stage buffer self-consumed last iteration).
        if (ch + 1 < NCHUNK) {
            stage_chunk(sbase + OFF_STG, xa + (ch + 1) * KC, wa + (ch + 1) * KC);
        } else {
            asm volatile("cp.async.commit_group;" ::: "memory");
        }

        // MMA on buf[ch&1]: 2 terms (ah*bh + ah*bl), term-outer ordering
        const uint32_t buf = (uint32_t)((ch & 1) * BUF_SZ);
#pragma unroll
        for (int ks = 0; ks < 2; ++ks) {
            uint32_t ah[4][4], bh[2][4], bl[2][4];
#pragma unroll
            for (int mt = 0; mt < 4; ++mt) {
                uint32_t addr = sbase + buf + T_AH +
                                (a_row + mt * 16) * ROWB + ks * 32 + a_cb;
                ldm_x4(ah[mt], addr);
            }
#pragma unroll
            for (int bt = 0; bt < 2; ++bt) {
                uint32_t addr = sbase + buf + T_BH +
                                (b_row + bt * 16) * ROWB + ks * 32 + b_cb;
                ldm_x4(bh[bt], addr);
                ldm_x4(bl[bt], addr + (T_BL - T_BH));
            }
#pragma unroll
            for (int mt = 0; mt < 4; ++mt)
#pragma unroll
                for (int nt = 0; nt < 4; ++nt)
                    mma_f16(acc[mt][nt], ah[mt], &bh[nt >> 1][(nt & 1) * 2]);
#pragma unroll
            for (int mt = 0; mt < 4; ++mt)
#pragma unroll
                for (int nt = 0; nt < 4; ++nt)
                    mma_f16(acc[mt][nt], ah[mt], &bl[nt >> 1][(nt & 1) * 2]);
        }

        // Convert chunk ch+1 into buf[(ch+1)&1] (own staged data only)
        asm volatile("cp.async.wait_group 0;" ::: "memory");
        if (ch + 1 < NCHUNK) {
            convert_stage(sm, (uint32_t)(((ch + 1) & 1) * BUF_SZ));
        }
        __syncthreads();
    }

    // Epilogue: add bias, store. out[b][o][i] = b*65536 + o*64 + i
    const float* bp = bias + (size_t)(otile * 128) * IDIM + i_idx;
    float bv[4][2];
#pragma unroll
    for (int nt = 0; nt < 4; ++nt) {
        int n_l = warp_n * 32 + nt * 8 + 2 * (lid & 3);
        bv[nt][0] = bp[(size_t)n_l * IDIM];
        bv[nt][1] = bp[(size_t)(n_l + 1) * IDIM];
    }
#pragma unroll
    for (int mt = 0; mt < 4; ++mt) {
        int m0 = warp_m * 64 + mt * 16 + (lid >> 2);
#pragma unroll
        for (int nt = 0; nt < 4; ++nt) {
            int n_l = warp_n * 32 + nt * 8 + 2 * (lid & 3);
            float* o0 = out + (size_t)m0 * (ODIM * IDIM) +
                        (size_t)(otile * 128 + n_l) * IDIM + i_idx;
            o0[0] = acc[mt][nt][0] + bv[nt][0];
            o0[IDIM] = acc[mt][nt][1] + bv[nt][1];
            float* o8 = o0 + (size_t)8 * (ODIM * IDIM);
            o8[0] = acc[mt][nt][2] + bv[nt][0];
            o8[IDIM] = acc[mt][nt][3] + bv[nt][1];
        }
    }
}

extern "C" void kernel_launch(void* const* d_in, const int* in_sizes, int n_in,
                              void* d_out, int out_size) {
    (void)in_sizes; (void)n_in; (void)out_size;
    const float* x = (const float*)d_in[0];
    const float* w = (const float*)d_in[1];
    const float* bias = (const float*)d_in[2];
    float* out = (float*)d_out;

    cudaFuncSetAttribute(fl_kernel, cudaFuncAttributeMaxDynamicSharedMemorySize,
                         SMEM_DYN);
    fl_kernel<<<dim3(ODIM / 128, IDIM), THREADS, SMEM_DYN>>>(x, w, bias, out);
}